// round 11
// baseline (speedup 1.0000x reference)
#include <cuda_runtime.h>
#include <cuda_fp16.h>
#include <math.h>
#include <cstdint>

#define NMAX 100000
#define EMAX 1600000
#define D 64
#define KDIM 192
#define OUTC 64
#define BCAP 64                     // bucket capacity (P(deg>64) ~ 2e-18/node)

typedef unsigned long long u64;

// ---- scratch ----
__device__ int   g_cnt[NMAX];       // zero-init; self-cleaned by aggregate
__device__ int   g_adjb[(size_t)NMAX * BCAP];
__device__ uint2 g_feat16[(size_t)NMAX * 16];   // [N, 64] fp16, 4 dims per uint2
__device__ float g_comb[(size_t)NMAX * KDIM];   // [N, 192] sum|max|min

// ---------------- feature fp32 -> fp16 conversion ----------------

__global__ __launch_bounds__(256) void featcvt_kernel(const float* __restrict__ feat, int total4) {
    int i = blockIdx.x * blockDim.x + threadIdx.x;   // over N*D/4
    if (i < total4) {
        float4 v = *(const float4*)&feat[(size_t)i * 4];
        __half2 h0 = __floats2half2_rn(v.x, v.y);
        __half2 h1 = __floats2half2_rn(v.z, v.w);
        uint2 u;
        u.x = *(uint32_t*)&h0;
        u.y = *(uint32_t*)&h1;
        g_feat16[i] = u;
    }
}

// ---------------- bucketed adjacency build (replaces hist+scan+scatter) ----------------

__global__ void bucket_kernel(const int* __restrict__ row,
                              const int* __restrict__ col, int E) {
    int i = blockIdx.x * blockDim.x + threadIdx.x;
    if (i < E) {
        int r = row[i];
        int slot = atomicAdd(&g_cnt[r], 1);
        if (slot < BCAP) g_adjb[(size_t)r * BCAP + slot] = col[i];
    }
}

// ---------------- aggregation: half-warp per node, fp16 gathers ----------------
// 16 lanes x 4 dims (uint2 = 2 half2) = 64 dims; 128B per edge per half-warp.
// max/min in half2 SIMD (monotonic => exact picks), sum accumulated in fp32.
// Reads degree from g_cnt and resets it (deterministic across graph replays).

__device__ __forceinline__ void acc16(float4& sm, __half2& mxa, __half2& mxb,
                                      __half2& mna, __half2& mnb, uint2 u) {
    __half2 h0 = *(__half2*)&u.x;
    __half2 h1 = *(__half2*)&u.y;
    mxa = __hmax2(mxa, h0);  mxb = __hmax2(mxb, h1);
    mna = __hmin2(mna, h0);  mnb = __hmin2(mnb, h1);
    float2 f0 = __half22float2(h0);
    float2 f1 = __half22float2(h1);
    sm.x += f0.x;  sm.y += f0.y;  sm.z += f1.x;  sm.w += f1.y;
}

__global__ __launch_bounds__(256) void aggregate_kernel(int n) {
    int gt   = blockIdx.x * blockDim.x + threadIdx.x;
    int node = gt >> 4;
    int lane = gt & 15;
    if (node >= n) return;

    int deg = g_cnt[node];                    // broadcast load
    if (lane == 0) g_cnt[node] = 0;           // self-clean for next call
    deg = min(deg, BCAP);
    const int* bk = &g_adjb[(size_t)node * BCAP];

    float4 sm = make_float4(0.f, 0.f, 0.f, 0.f);
    __half2 ninf2 = __float2half2_rn(-INFINITY);
    __half2 pinf2 = __float2half2_rn( INFINITY);
    __half2 mxa = ninf2, mxb = ninf2;
    __half2 mna = pinf2, mnb = pinf2;

    int j = 0;
    for (; j + 4 <= deg; j += 4) {
        int c0 = __ldg(&bk[j]);
        int c1 = __ldg(&bk[j + 1]);
        int c2 = __ldg(&bk[j + 2]);
        int c3 = __ldg(&bk[j + 3]);
        uint2 u0 = g_feat16[(size_t)c0 * 16 + lane];
        uint2 u1 = g_feat16[(size_t)c1 * 16 + lane];
        uint2 u2 = g_feat16[(size_t)c2 * 16 + lane];
        uint2 u3 = g_feat16[(size_t)c3 * 16 + lane];
        acc16(sm, mxa, mxb, mna, mnb, u0);
        acc16(sm, mxa, mxb, mna, mnb, u1);
        acc16(sm, mxa, mxb, mna, mnb, u2);
        acc16(sm, mxa, mxb, mna, mnb, u3);
    }
    for (; j < deg; j++) {
        int c0 = __ldg(&bk[j]);
        uint2 u0 = g_feat16[(size_t)c0 * 16 + lane];
        acc16(sm, mxa, mxb, mna, mnb, u0);
    }

    float4 mx, mn;
    {
        float2 a = __half22float2(mxa), bq = __half22float2(mxb);
        mx = make_float4(a.x, a.y, bq.x, bq.y);
        float2 c = __half22float2(mna), dq = __half22float2(mnb);
        mn = make_float4(c.x, c.y, dq.x, dq.y);
    }
    if (deg == 0) {
        mx = make_float4(0.f, 0.f, 0.f, 0.f);
        mn = make_float4(0.f, 0.f, 0.f, 0.f);
    }

    float* cb = &g_comb[(size_t)node * KDIM];
    *(float4*)&cb[        4 * lane] = sm;
    *(float4*)&cb[ D  +   4 * lane] = mx;
    *(float4*)&cb[2*D +   4 * lane] = mn;
}

// ---------------- MLP GEMM with packed f32x2 FMA ----------------

__device__ __forceinline__ u64 pack2(float lo, float hi) {
    u64 r; asm("mov.b64 %0, {%1, %2};" : "=l"(r) : "f"(lo), "f"(hi)); return r;
}
__device__ __forceinline__ void ffma2(u64& d, u64 a, u64 b) {
    asm("fma.rn.f32x2 %0, %1, %2, %0;" : "+l"(d) : "l"(a), "l"(b));
}
__device__ __forceinline__ float2 unpack2(u64 v) {
    float2 f; asm("mov.b64 {%0, %1}, %2;" : "=f"(f.x), "=f"(f.y) : "l"(v)); return f;
}

#define BM 128
#define BK 16
#define BN 64

__global__ __launch_bounds__(256) void mlp_gemm_kernel(
    const float* __restrict__ Wg,     // [192,64]
    const float* __restrict__ bg,     // [64]
    float* __restrict__ out, int n)
{
    __shared__ float As[BK][BM];
    __shared__ float Bs[BK][BN];

    const float* __restrict__ A = g_comb;

    int tid = threadIdx.x;
    int block_m = blockIdx.x * BM;
    int tx = tid & 15;
    int ty = tid >> 4;

    int a_row  = tid >> 2;
    int a_col4 = (tid & 3) * 4;
    int b_row  = tid >> 4;
    int b_col4 = (tid & 15) * 4;

    u64 acc[4][4];
    #pragma unroll
    for (int i = 0; i < 4; i++)
        #pragma unroll
        for (int j = 0; j < 4; j++) acc[i][j] = 0ull;

    for (int k0 = 0; k0 < KDIM; k0 += BK) {
        #pragma unroll
        for (int r = 0; r < 2; r++) {
            int m  = a_row + r * 64;
            int gm = block_m + m;
            float4 v = make_float4(0.f, 0.f, 0.f, 0.f);
            if (gm < n) v = *(const float4*)&A[(size_t)gm * KDIM + k0 + a_col4];
            As[a_col4 + 0][m] = v.x;
            As[a_col4 + 1][m] = v.y;
            As[a_col4 + 2][m] = v.z;
            As[a_col4 + 3][m] = v.w;
        }
        *(float4*)&Bs[b_row][b_col4] =
            *(const float4*)&Wg[(size_t)(k0 + b_row) * BN + b_col4];
        __syncthreads();

        #pragma unroll
        for (int k = 0; k < BK; k++) {
            u64 ra[4];
            #pragma unroll
            for (int i = 0; i < 4; i++)
                ra[i] = *(const u64*)&As[k][ty * 8 + 2 * i];
            float4 rbv = *(const float4*)&Bs[k][tx * 4];
            u64 rb[4];
            rb[0] = pack2(rbv.x, rbv.x);
            rb[1] = pack2(rbv.y, rbv.y);
            rb[2] = pack2(rbv.z, rbv.z);
            rb[3] = pack2(rbv.w, rbv.w);
            #pragma unroll
            for (int i = 0; i < 4; i++)
                #pragma unroll
                for (int j = 0; j < 4; j++)
                    ffma2(acc[i][j], ra[i], rb[j]);
        }
        __syncthreads();
    }

    float4 bv = *(const float4*)&bg[tx * 4];
    #pragma unroll
    for (int i = 0; i < 4; i++) {
        float2 c0 = unpack2(acc[i][0]);
        float2 c1 = unpack2(acc[i][1]);
        float2 c2 = unpack2(acc[i][2]);
        float2 c3 = unpack2(acc[i][3]);
        int gm0 = block_m + ty * 8 + 2 * i;
        if (gm0 < n) {
            float4 o;
            o.x = tanhf(c0.x + bv.x); o.y = tanhf(c1.x + bv.y);
            o.z = tanhf(c2.x + bv.z); o.w = tanhf(c3.x + bv.w);
            *(float4*)&out[(size_t)gm0 * OUTC + tx * 4] = o;
        }
        if (gm0 + 1 < n) {
            float4 o;
            o.x = tanhf(c0.y + bv.x); o.y = tanhf(c1.y + bv.y);
            o.z = tanhf(c2.y + bv.z); o.w = tanhf(c3.y + bv.w);
            *(float4*)&out[(size_t)(gm0 + 1) * OUTC + tx * 4] = o;
        }
    }
}

// ---------------- launch ----------------

extern "C" void kernel_launch(void* const* d_in, const int* in_sizes, int n_in,
                              void* d_out, int out_size) {
    const int*   row  = (const int*)d_in[0];
    const int*   col  = (const int*)d_in[1];
    const float* feat = (const float*)d_in[2];
    const float* W    = (const float*)d_in[3];
    const float* b    = (const float*)d_in[4];
    float* out = (float*)d_out;

    int E = in_sizes[0];
    int N = in_sizes[2] / D;
    int total4 = N * D / 4;

    featcvt_kernel<<<(total4 + 255) / 256, 256>>>(feat, total4);
    bucket_kernel<<<(E + 255) / 256, 256>>>(row, col, E);
    aggregate_kernel<<<(N * 16 + 255) / 256, 256>>>(N);
    mlp_gemm_kernel<<<(N + BM - 1) / BM, 256>>>(W, b, out, N);
}

// round 12
// speedup vs baseline: 1.2582x; 1.2582x over previous
#include <cuda_runtime.h>
#include <cuda_fp16.h>
#include <math.h>
#include <cstdint>

#define NMAX 100000
#define EMAX 1600000
#define D 64
#define KDIM 192
#define OUTC 64

typedef unsigned long long u64;

// ---- scratch ----
__device__ int   g_cnt[NMAX];          // zero-init; self-cleaned by scan_partial
__device__ int   g_start[NMAX + 1];
__device__ int   g_cursor[NMAX];
__device__ int   g_adj[EMAX];
__device__ int   g_bsum[260];
__device__ uint2 g_feat16[(size_t)NMAX * 16];   // [N, 64] fp16, 4 dims per uint2
__device__ float g_comb[(size_t)NMAX * KDIM];   // [N, 192] sum|max|min

// ---------------- feature fp32 -> fp16 conversion ----------------

__global__ __launch_bounds__(256) void featcvt_kernel(const float* __restrict__ feat, int total4) {
    int i = blockIdx.x * blockDim.x + threadIdx.x;
    if (i < total4) {
        float4 v = *(const float4*)&feat[(size_t)i * 4];
        __half2 h0 = __floats2half2_rn(v.x, v.y);
        __half2 h1 = __floats2half2_rn(v.z, v.w);
        uint2 u;
        u.x = *(uint32_t*)&h0;
        u.y = *(uint32_t*)&h1;
        g_feat16[i] = u;
    }
}

// ---------------- CSR build ----------------

__global__ void hist_kernel(const int* __restrict__ row, int E) {
    int i = blockIdx.x * blockDim.x + threadIdx.x;
    if (i < E) atomicAdd(&g_cnt[row[i]], 1);
}

#define SCAN_B 512

__global__ __launch_bounds__(SCAN_B) void scan_partial_kernel(int n) {
    __shared__ int ws[16];
    int blk = blockIdx.x, tid = threadIdx.x;
    int i = blk * SCAN_B + tid;
    int v = (i < n) ? g_cnt[i] : 0;
    if (i < n) g_cnt[i] = 0;                   // self-clean for next call
    int lane = tid & 31, wid = tid >> 5;
    int x = v;
    #pragma unroll
    for (int o = 1; o < 32; o <<= 1) {
        int y = __shfl_up_sync(0xffffffffu, x, o);
        if (lane >= o) x += y;
    }
    if (lane == 31) ws[wid] = x;
    __syncthreads();
    if (wid == 0 && lane < 16) {
        int w = ws[lane];
        #pragma unroll
        for (int o = 1; o < 16; o <<= 1) {
            int y = __shfl_up_sync(0x0000ffffu, w, o);
            if (lane >= o) w += y;
        }
        ws[lane] = w;
    }
    __syncthreads();
    int incl = x + (wid > 0 ? ws[wid - 1] : 0);
    if (i < n) g_start[i] = incl - v;
    if (tid == SCAN_B - 1) g_bsum[blk] = incl;
}

__global__ __launch_bounds__(SCAN_B) void scan_add_kernel(int n, int nb) {
    __shared__ int ws[16];
    int bid = blockIdx.x, tid = threadIdx.x;
    int lane = tid & 31, wid = tid >> 5;

    int v = (tid < bid) ? g_bsum[tid] : 0;
    #pragma unroll
    for (int o = 16; o > 0; o >>= 1) v += __shfl_down_sync(0xffffffffu, v, o);
    if (lane == 0) ws[wid] = v;
    __syncthreads();
    if (wid == 0) {
        int w = (lane < 16) ? ws[lane] : 0;
        #pragma unroll
        for (int o = 8; o > 0; o >>= 1) w += __shfl_down_sync(0xffffffffu, w, o);
        if (lane == 0) ws[0] = w;
    }
    __syncthreads();
    int off = ws[0];

    int i = bid * SCAN_B + tid;
    if (i < n) {
        int s = g_start[i] + off;
        g_start[i] = s;
        g_cursor[i] = s;
    }
    if (tid == 0 && bid == nb - 1) g_start[n] = off + g_bsum[bid];
}

__global__ void scatter_kernel(const int* __restrict__ row,
                               const int* __restrict__ col, int E) {
    int i = blockIdx.x * blockDim.x + threadIdx.x;
    if (i < E) {
        int p = atomicAdd(&g_cursor[row[i]], 1);
        g_adj[p] = col[i];
    }
}

// ---------------- aggregation: half-warp per node, fp16 gathers ----------------

__device__ __forceinline__ void acc16(float4& sm, __half2& mxa, __half2& mxb,
                                      __half2& mna, __half2& mnb, uint2 u) {
    __half2 h0 = *(__half2*)&u.x;
    __half2 h1 = *(__half2*)&u.y;
    mxa = __hmax2(mxa, h0);  mxb = __hmax2(mxb, h1);
    mna = __hmin2(mna, h0);  mnb = __hmin2(mnb, h1);
    float2 f0 = __half22float2(h0);
    float2 f1 = __half22float2(h1);
    sm.x += f0.x;  sm.y += f0.y;  sm.z += f1.x;  sm.w += f1.y;
}

__global__ __launch_bounds__(256) void aggregate_kernel(int n) {
    int gt   = blockIdx.x * blockDim.x + threadIdx.x;
    int node = gt >> 4;
    int lane = gt & 15;
    if (node >= n) return;

    int s = g_start[node];
    int e = g_start[node + 1];

    float4 sm = make_float4(0.f, 0.f, 0.f, 0.f);
    __half2 ninf2 = __float2half2_rn(-INFINITY);
    __half2 pinf2 = __float2half2_rn( INFINITY);
    __half2 mxa = ninf2, mxb = ninf2;
    __half2 mna = pinf2, mnb = pinf2;

    int j = s;
    for (; j + 4 <= e; j += 4) {
        int c0 = __ldg(&g_adj[j]);
        int c1 = __ldg(&g_adj[j + 1]);
        int c2 = __ldg(&g_adj[j + 2]);
        int c3 = __ldg(&g_adj[j + 3]);
        uint2 u0 = g_feat16[(size_t)c0 * 16 + lane];
        uint2 u1 = g_feat16[(size_t)c1 * 16 + lane];
        uint2 u2 = g_feat16[(size_t)c2 * 16 + lane];
        uint2 u3 = g_feat16[(size_t)c3 * 16 + lane];
        acc16(sm, mxa, mxb, mna, mnb, u0);
        acc16(sm, mxa, mxb, mna, mnb, u1);
        acc16(sm, mxa, mxb, mna, mnb, u2);
        acc16(sm, mxa, mxb, mna, mnb, u3);
    }
    for (; j < e; j++) {
        int c0 = __ldg(&g_adj[j]);
        uint2 u0 = g_feat16[(size_t)c0 * 16 + lane];
        acc16(sm, mxa, mxb, mna, mnb, u0);
    }

    float4 mx, mn;
    {
        float2 a = __half22float2(mxa), bq = __half22float2(mxb);
        mx = make_float4(a.x, a.y, bq.x, bq.y);
        float2 c = __half22float2(mna), dq = __half22float2(mnb);
        mn = make_float4(c.x, c.y, dq.x, dq.y);
    }
    if (e == s) {
        mx = make_float4(0.f, 0.f, 0.f, 0.f);
        mn = make_float4(0.f, 0.f, 0.f, 0.f);
    }

    float* cb = &g_comb[(size_t)node * KDIM];
    *(float4*)&cb[        4 * lane] = sm;
    *(float4*)&cb[ D  +   4 * lane] = mx;
    *(float4*)&cb[2*D +   4 * lane] = mn;
}

// ---------------- MLP GEMM: FFMA2 + register double-buffer + MUFU.TANH ----------------

__device__ __forceinline__ u64 pack2(float lo, float hi) {
    u64 r; asm("mov.b64 %0, {%1, %2};" : "=l"(r) : "f"(lo), "f"(hi)); return r;
}
__device__ __forceinline__ void ffma2(u64& d, u64 a, u64 b) {
    asm("fma.rn.f32x2 %0, %1, %2, %0;" : "+l"(d) : "l"(a), "l"(b));
}
__device__ __forceinline__ float2 unpack2(u64 v) {
    float2 f; asm("mov.b64 {%0, %1}, %2;" : "=f"(f.x), "=f"(f.y) : "l"(v)); return f;
}
__device__ __forceinline__ float tanh_fast(float x) {
    float y; asm("tanh.approx.f32 %0, %1;" : "=f"(y) : "f"(x)); return y;
}

#define BM 128
#define BK 16
#define BN 64
#define NTILES (KDIM / BK)

__global__ __launch_bounds__(256) void mlp_gemm_kernel(
    const float* __restrict__ Wg,     // [192,64]
    const float* __restrict__ bg,     // [64]
    float* __restrict__ out, int n)
{
    __shared__ float As[BK][BM];
    __shared__ float Bs[BK][BN];

    const float* __restrict__ A = g_comb;

    int tid = threadIdx.x;
    int block_m = blockIdx.x * BM;
    int tx = tid & 15;
    int ty = tid >> 4;

    int a_row  = tid >> 2;
    int a_col4 = (tid & 3) * 4;
    int b_row  = tid >> 4;
    int b_col4 = (tid & 15) * 4;

    int gm0a = block_m + a_row;
    int gm1a = block_m + a_row + 64;

    u64 acc[4][4];
    #pragma unroll
    for (int i = 0; i < 4; i++)
        #pragma unroll
        for (int j = 0; j < 4; j++) acc[i][j] = 0ull;

    float4 va0, va1, vbv;
    // preload tile 0 into registers
    va0 = (gm0a < n) ? *(const float4*)&A[(size_t)gm0a * KDIM + a_col4]
                     : make_float4(0.f, 0.f, 0.f, 0.f);
    va1 = (gm1a < n) ? *(const float4*)&A[(size_t)gm1a * KDIM + a_col4]
                     : make_float4(0.f, 0.f, 0.f, 0.f);
    vbv = *(const float4*)&Wg[(size_t)b_row * BN + b_col4];

    for (int t = 0; t < NTILES; t++) {
        // store current tile regs -> smem
        As[a_col4 + 0][a_row] = va0.x;
        As[a_col4 + 1][a_row] = va0.y;
        As[a_col4 + 2][a_row] = va0.z;
        As[a_col4 + 3][a_row] = va0.w;
        As[a_col4 + 0][a_row + 64] = va1.x;
        As[a_col4 + 1][a_row + 64] = va1.y;
        As[a_col4 + 2][a_row + 64] = va1.z;
        As[a_col4 + 3][a_row + 64] = va1.w;
        *(float4*)&Bs[b_row][b_col4] = vbv;
        __syncthreads();

        // prefetch next tile into registers (LDG hidden under compute below)
        if (t + 1 < NTILES) {
            int k0n = (t + 1) * BK;
            va0 = (gm0a < n) ? *(const float4*)&A[(size_t)gm0a * KDIM + k0n + a_col4]
                             : make_float4(0.f, 0.f, 0.f, 0.f);
            va1 = (gm1a < n) ? *(const float4*)&A[(size_t)gm1a * KDIM + k0n + a_col4]
                             : make_float4(0.f, 0.f, 0.f, 0.f);
            vbv = *(const float4*)&Wg[(size_t)(k0n + b_row) * BN + b_col4];
        }

        #pragma unroll
        for (int k = 0; k < BK; k++) {
            u64 ra[4];
            #pragma unroll
            for (int i = 0; i < 4; i++)
                ra[i] = *(const u64*)&As[k][ty * 8 + 2 * i];
            float4 rbv = *(const float4*)&Bs[k][tx * 4];
            u64 rb[4];
            rb[0] = pack2(rbv.x, rbv.x);
            rb[1] = pack2(rbv.y, rbv.y);
            rb[2] = pack2(rbv.z, rbv.z);
            rb[3] = pack2(rbv.w, rbv.w);
            #pragma unroll
            for (int i = 0; i < 4; i++)
                #pragma unroll
                for (int j = 0; j < 4; j++)
                    ffma2(acc[i][j], ra[i], rb[j]);
        }
        __syncthreads();
    }

    float4 bv = *(const float4*)&bg[tx * 4];
    #pragma unroll
    for (int i = 0; i < 4; i++) {
        float2 c0 = unpack2(acc[i][0]);
        float2 c1 = unpack2(acc[i][1]);
        float2 c2 = unpack2(acc[i][2]);
        float2 c3 = unpack2(acc[i][3]);
        int gm0 = block_m + ty * 8 + 2 * i;
        if (gm0 < n) {
            float4 o;
            o.x = tanh_fast(c0.x + bv.x); o.y = tanh_fast(c1.x + bv.y);
            o.z = tanh_fast(c2.x + bv.z); o.w = tanh_fast(c3.x + bv.w);
            *(float4*)&out[(size_t)gm0 * OUTC + tx * 4] = o;
        }
        if (gm0 + 1 < n) {
            float4 o;
            o.x = tanh_fast(c0.y + bv.x); o.y = tanh_fast(c1.y + bv.y);
            o.z = tanh_fast(c2.y + bv.z); o.w = tanh_fast(c3.y + bv.w);
            *(float4*)&out[(size_t)(gm0 + 1) * OUTC + tx * 4] = o;
        }
    }
}

// ---------------- launch ----------------

extern "C" void kernel_launch(void* const* d_in, const int* in_sizes, int n_in,
                              void* d_out, int out_size) {
    const int*   row  = (const int*)d_in[0];
    const int*   col  = (const int*)d_in[1];
    const float* feat = (const float*)d_in[2];
    const float* W    = (const float*)d_in[3];
    const float* b    = (const float*)d_in[4];
    float* out = (float*)d_out;

    int E = in_sizes[0];
    int N = in_sizes[2] / D;
    int nb = (N + SCAN_B - 1) / SCAN_B;
    int total4 = N * D / 4;

    featcvt_kernel<<<(total4 + 255) / 256, 256>>>(feat, total4);
    hist_kernel<<<(E + 255) / 256, 256>>>(row, E);
    scan_partial_kernel<<<nb, SCAN_B>>>(N);
    scan_add_kernel<<<nb, SCAN_B>>>(N, nb);
    scatter_kernel<<<(E + 255) / 256, 256>>>(row, col, E);
    aggregate_kernel<<<(N * 16 + 255) / 256, 256>>>(N);
    mlp_gemm_kernel<<<(N + BM - 1) / BM, 256>>>(W, b, out, N);
}

// round 13
// speedup vs baseline: 1.2596x; 1.0011x over previous
#include <cuda_runtime.h>
#include <cuda_fp16.h>
#include <math.h>
#include <cstdint>

#define NMAX 100000
#define EMAX 1600000
#define D 64
#define KDIM 192
#define OUTC 64

typedef unsigned long long u64;

// ---- scratch ----
__device__ int   g_cnt[NMAX];          // zero-init; self-cleaned by scan_partial
__device__ int   g_start[NMAX + 1];
__device__ int   g_cursor[NMAX];
__device__ int   g_adj[EMAX];
__device__ int   g_bsum[260];
__device__ uint2 g_feat16[(size_t)NMAX * 16];   // [N, 64] fp16, 4 dims per uint2
__device__ float g_comb[(size_t)NMAX * KDIM];   // [N, 192] sum|max|min

// ---------------- feature fp32 -> fp16 conversion ----------------

__global__ __launch_bounds__(256) void featcvt_kernel(const float* __restrict__ feat, int total4) {
    int i = blockIdx.x * blockDim.x + threadIdx.x;
    if (i < total4) {
        float4 v = *(const float4*)&feat[(size_t)i * 4];
        __half2 h0 = __floats2half2_rn(v.x, v.y);
        __half2 h1 = __floats2half2_rn(v.z, v.w);
        uint2 u;
        u.x = *(uint32_t*)&h0;
        u.y = *(uint32_t*)&h1;
        g_feat16[i] = u;
    }
}

// ---------------- CSR build ----------------

__global__ void hist_kernel(const int* __restrict__ row, int E) {
    int i = blockIdx.x * blockDim.x + threadIdx.x;
    if (i < E) atomicAdd(&g_cnt[row[i]], 1);
}

#define SCAN_B 512

__global__ __launch_bounds__(SCAN_B) void scan_partial_kernel(int n) {
    __shared__ int ws[16];
    int blk = blockIdx.x, tid = threadIdx.x;
    int i = blk * SCAN_B + tid;
    int v = (i < n) ? g_cnt[i] : 0;
    if (i < n) g_cnt[i] = 0;                   // self-clean for next call
    int lane = tid & 31, wid = tid >> 5;
    int x = v;
    #pragma unroll
    for (int o = 1; o < 32; o <<= 1) {
        int y = __shfl_up_sync(0xffffffffu, x, o);
        if (lane >= o) x += y;
    }
    if (lane == 31) ws[wid] = x;
    __syncthreads();
    if (wid == 0 && lane < 16) {
        int w = ws[lane];
        #pragma unroll
        for (int o = 1; o < 16; o <<= 1) {
            int y = __shfl_up_sync(0x0000ffffu, w, o);
            if (lane >= o) w += y;
        }
        ws[lane] = w;
    }
    __syncthreads();
    int incl = x + (wid > 0 ? ws[wid - 1] : 0);
    if (i < n) g_start[i] = incl - v;
    if (tid == SCAN_B - 1) g_bsum[blk] = incl;
}

__global__ __launch_bounds__(SCAN_B) void scan_add_kernel(int n, int nb) {
    __shared__ int ws[16];
    int bid = blockIdx.x, tid = threadIdx.x;
    int lane = tid & 31, wid = tid >> 5;

    int v = (tid < bid) ? g_bsum[tid] : 0;
    #pragma unroll
    for (int o = 16; o > 0; o >>= 1) v += __shfl_down_sync(0xffffffffu, v, o);
    if (lane == 0) ws[wid] = v;
    __syncthreads();
    if (wid == 0) {
        int w = (lane < 16) ? ws[lane] : 0;
        #pragma unroll
        for (int o = 8; o > 0; o >>= 1) w += __shfl_down_sync(0xffffffffu, w, o);
        if (lane == 0) ws[0] = w;
    }
    __syncthreads();
    int off = ws[0];

    int i = bid * SCAN_B + tid;
    if (i < n) {
        int s = g_start[i] + off;
        g_start[i] = s;
        g_cursor[i] = s;
    }
    if (tid == 0 && bid == nb - 1) g_start[n] = off + g_bsum[bid];
}

__global__ void scatter_kernel(const int* __restrict__ row,
                               const int* __restrict__ col, int E) {
    int i = blockIdx.x * blockDim.x + threadIdx.x;
    if (i < E) {
        int p = atomicAdd(&g_cursor[row[i]], 1);
        g_adj[p] = col[i];
    }
}

// ---------------- aggregation: half-warp per node, fp16 gathers ----------------

__device__ __forceinline__ void acc16(float4& sm, __half2& mxa, __half2& mxb,
                                      __half2& mna, __half2& mnb, uint2 u) {
    __half2 h0 = *(__half2*)&u.x;
    __half2 h1 = *(__half2*)&u.y;
    mxa = __hmax2(mxa, h0);  mxb = __hmax2(mxb, h1);
    mna = __hmin2(mna, h0);  mnb = __hmin2(mnb, h1);
    float2 f0 = __half22float2(h0);
    float2 f1 = __half22float2(h1);
    sm.x += f0.x;  sm.y += f0.y;  sm.z += f1.x;  sm.w += f1.y;
}

__global__ __launch_bounds__(256) void aggregate_kernel(int n) {
    int gt   = blockIdx.x * blockDim.x + threadIdx.x;
    int node = gt >> 4;
    int lane = gt & 15;
    if (node >= n) return;

    int s = g_start[node];
    int e = g_start[node + 1];

    float4 sm = make_float4(0.f, 0.f, 0.f, 0.f);
    __half2 ninf2 = __float2half2_rn(-INFINITY);
    __half2 pinf2 = __float2half2_rn( INFINITY);
    __half2 mxa = ninf2, mxb = ninf2;
    __half2 mna = pinf2, mnb = pinf2;

    int j = s;
    for (; j + 4 <= e; j += 4) {
        int c0 = __ldg(&g_adj[j]);
        int c1 = __ldg(&g_adj[j + 1]);
        int c2 = __ldg(&g_adj[j + 2]);
        int c3 = __ldg(&g_adj[j + 3]);
        uint2 u0 = g_feat16[(size_t)c0 * 16 + lane];
        uint2 u1 = g_feat16[(size_t)c1 * 16 + lane];
        uint2 u2 = g_feat16[(size_t)c2 * 16 + lane];
        uint2 u3 = g_feat16[(size_t)c3 * 16 + lane];
        acc16(sm, mxa, mxb, mna, mnb, u0);
        acc16(sm, mxa, mxb, mna, mnb, u1);
        acc16(sm, mxa, mxb, mna, mnb, u2);
        acc16(sm, mxa, mxb, mna, mnb, u3);
    }
    for (; j < e; j++) {
        int c0 = __ldg(&g_adj[j]);
        uint2 u0 = g_feat16[(size_t)c0 * 16 + lane];
        acc16(sm, mxa, mxb, mna, mnb, u0);
    }

    float4 mx, mn;
    {
        float2 a = __half22float2(mxa), bq = __half22float2(mxb);
        mx = make_float4(a.x, a.y, bq.x, bq.y);
        float2 c = __half22float2(mna), dq = __half22float2(mnb);
        mn = make_float4(c.x, c.y, dq.x, dq.y);
    }
    if (e == s) {
        mx = make_float4(0.f, 0.f, 0.f, 0.f);
        mn = make_float4(0.f, 0.f, 0.f, 0.f);
    }

    float* cb = &g_comb[(size_t)node * KDIM];
    *(float4*)&cb[        4 * lane] = sm;
    *(float4*)&cb[ D  +   4 * lane] = mx;
    *(float4*)&cb[2*D +   4 * lane] = mn;
}

// ---------------- MLP GEMM: 8x8 register tile, FFMA2, 128 threads ----------------

__device__ __forceinline__ u64 pack2(float lo, float hi) {
    u64 r; asm("mov.b64 %0, {%1, %2};" : "=l"(r) : "f"(lo), "f"(hi)); return r;
}
__device__ __forceinline__ void ffma2(u64& d, u64 a, u64 b) {
    asm("fma.rn.f32x2 %0, %1, %2, %0;" : "+l"(d) : "l"(a), "l"(b));
}
__device__ __forceinline__ float2 unpack2(u64 v) {
    float2 f; asm("mov.b64 {%0, %1}, %2;" : "=f"(f.x), "=f"(f.y) : "l"(v)); return f;
}
__device__ __forceinline__ float tanh_fast(float x) {
    float y; asm("tanh.approx.f32 %0, %1;" : "=f"(y) : "f"(x)); return y;
}

#define BM 128
#define BK 16
#define BN 64
#define NTILES (KDIM / BK)
#define SAS 130                      // As k-row stride (even -> 8B-aligned LDS.64)

__global__ __launch_bounds__(128) void mlp_gemm_kernel(
    const float* __restrict__ Wg,     // [192,64]
    const float* __restrict__ bg,     // [64]
    float* __restrict__ out, int n)
{
    __shared__ float As[BK * SAS];    // k-major [16][130]
    __shared__ float Bs[BK][BN];

    const float* __restrict__ A = g_comb;

    int tid = threadIdx.x;
    int block_m = blockIdx.x * BM;
    int tx = tid & 7;                 // 8 output cols
    int ty = tid >> 3;                // 8 output rows (4 row-pairs)

    // A tile load mapping: 128x16 floats, 4 float4/thread
    int ar[4], ac[4], agm[4];
    #pragma unroll
    for (int r = 0; r < 4; r++) {
        int idx = tid + 128 * r;
        ar[r] = idx >> 2;
        ac[r] = (idx & 3) * 4;
        agm[r] = block_m + ar[r];
    }
    // B tile: 16x64 floats, 2 float4/thread
    int br[2], bc[2];
    #pragma unroll
    for (int r = 0; r < 2; r++) {
        int idx = tid + 128 * r;
        br[r] = idx >> 4;
        bc[r] = (idx & 15) * 4;
    }

    u64 acc[4][8];
    #pragma unroll
    for (int i = 0; i < 4; i++)
        #pragma unroll
        for (int j = 0; j < 8; j++) acc[i][j] = 0ull;

    float4 va[4], vb[2];
    #pragma unroll
    for (int r = 0; r < 4; r++)
        va[r] = (agm[r] < n) ? *(const float4*)&A[(size_t)agm[r] * KDIM + ac[r]]
                             : make_float4(0.f, 0.f, 0.f, 0.f);
    #pragma unroll
    for (int r = 0; r < 2; r++)
        vb[r] = *(const float4*)&Wg[(size_t)br[r] * BN + bc[r]];

    for (int t = 0; t < NTILES; t++) {
        #pragma unroll
        for (int r = 0; r < 4; r++) {
            As[(ac[r] + 0) * SAS + ar[r]] = va[r].x;
            As[(ac[r] + 1) * SAS + ar[r]] = va[r].y;
            As[(ac[r] + 2) * SAS + ar[r]] = va[r].z;
            As[(ac[r] + 3) * SAS + ar[r]] = va[r].w;
        }
        #pragma unroll
        for (int r = 0; r < 2; r++)
            *(float4*)&Bs[br[r]][bc[r]] = vb[r];
        __syncthreads();

        if (t + 1 < NTILES) {
            int k0n = (t + 1) * BK;
            #pragma unroll
            for (int r = 0; r < 4; r++)
                va[r] = (agm[r] < n) ? *(const float4*)&A[(size_t)agm[r] * KDIM + k0n + ac[r]]
                                     : make_float4(0.f, 0.f, 0.f, 0.f);
            #pragma unroll
            for (int r = 0; r < 2; r++)
                vb[r] = *(const float4*)&Wg[(size_t)(k0n + br[r]) * BN + bc[r]];
        }

        #pragma unroll
        for (int k = 0; k < BK; k++) {
            u64 ra[4];
            #pragma unroll
            for (int i = 0; i < 4; i++)
                ra[i] = *(const u64*)&As[k * SAS + ty * 8 + 2 * i];
            float4 rb0 = *(const float4*)&Bs[k][tx * 8];
            float4 rb1 = *(const float4*)&Bs[k][tx * 8 + 4];
            u64 rb[8];
            rb[0] = pack2(rb0.x, rb0.x);
            rb[1] = pack2(rb0.y, rb0.y);
            rb[2] = pack2(rb0.z, rb0.z);
            rb[3] = pack2(rb0.w, rb0.w);
            rb[4] = pack2(rb1.x, rb1.x);
            rb[5] = pack2(rb1.y, rb1.y);
            rb[6] = pack2(rb1.z, rb1.z);
            rb[7] = pack2(rb1.w, rb1.w);
            #pragma unroll
            for (int i = 0; i < 4; i++)
                #pragma unroll
                for (int j = 0; j < 8; j++)
                    ffma2(acc[i][j], ra[i], rb[j]);
        }
        __syncthreads();
    }

    float4 bv0 = *(const float4*)&bg[tx * 8];
    float4 bv1 = *(const float4*)&bg[tx * 8 + 4];
    #pragma unroll
    for (int i = 0; i < 4; i++) {
        float2 c[8];
        #pragma unroll
        for (int j = 0; j < 8; j++) c[j] = unpack2(acc[i][j]);
        int gm0 = block_m + ty * 8 + 2 * i;
        if (gm0 < n) {
            float4 o0, o1;
            o0.x = tanh_fast(c[0].x + bv0.x); o0.y = tanh_fast(c[1].x + bv0.y);
            o0.z = tanh_fast(c[2].x + bv0.z); o0.w = tanh_fast(c[3].x + bv0.w);
            o1.x = tanh_fast(c[4].x + bv1.x); o1.y = tanh_fast(c[5].x + bv1.y);
            o1.z = tanh_fast(c[6].x + bv1.z); o1.w = tanh_fast(c[7].x + bv1.w);
            *(float4*)&out[(size_t)gm0 * OUTC + tx * 8]     = o0;
            *(float4*)&out[(size_t)gm0 * OUTC + tx * 8 + 4] = o1;
        }
        if (gm0 + 1 < n) {
            float4 o0, o1;
            o0.x = tanh_fast(c[0].y + bv0.x); o0.y = tanh_fast(c[1].y + bv0.y);
            o0.z = tanh_fast(c[2].y + bv0.z); o0.w = tanh_fast(c[3].y + bv0.w);
            o1.x = tanh_fast(c[4].y + bv1.x); o1.y = tanh_fast(c[5].y + bv1.y);
            o1.z = tanh_fast(c[6].y + bv1.z); o1.w = tanh_fast(c[7].y + bv1.w);
            *(float4*)&out[(size_t)(gm0 + 1) * OUTC + tx * 8]     = o0;
            *(float4*)&out[(size_t)(gm0 + 1) * OUTC + tx * 8 + 4] = o1;
        }
    }
}

// ---------------- launch ----------------

extern "C" void kernel_launch(void* const* d_in, const int* in_sizes, int n_in,
                              void* d_out, int out_size) {
    const int*   row  = (const int*)d_in[0];
    const int*   col  = (const int*)d_in[1];
    const float* feat = (const float*)d_in[2];
    const float* W    = (const float*)d_in[3];
    const float* b    = (const float*)d_in[4];
    float* out = (float*)d_out;

    int E = in_sizes[0];
    int N = in_sizes[2] / D;
    int nb = (N + SCAN_B - 1) / SCAN_B;
    int total4 = N * D / 4;

    featcvt_kernel<<<(total4 + 255) / 256, 256>>>(feat, total4);
    hist_kernel<<<(E + 255) / 256, 256>>>(row, E);
    scan_partial_kernel<<<nb, SCAN_B>>>(N);
    scan_add_kernel<<<nb, SCAN_B>>>(N, nb);
    scatter_kernel<<<(E + 255) / 256, 256>>>(row, col, E);
    aggregate_kernel<<<(N * 16 + 255) / 256, 256>>>(N);
    mlp_gemm_kernel<<<(N + BM - 1) / BM, 128>>>(W, b, out, N);
}

// round 14
// speedup vs baseline: 1.7682x; 1.4037x over previous
#include <cuda_runtime.h>
#include <cuda_fp16.h>
#include <math.h>
#include <cstdint>

#define NMAX 100000
#define EMAX 1600000
#define D 64
#define KDIM 192
#define OUTC 64

typedef unsigned long long u64;

// ---- scratch ----
__device__ int    g_cnt[NMAX];          // zero-init; self-cleaned by scan_partial
__device__ int    g_start[NMAX + 1];
__device__ int    g_cursor[NMAX];
__device__ int    g_adj[EMAX];
__device__ int    g_bsum[260];
__device__ uint2  g_feat16[(size_t)NMAX * 16];   // [N, 64] fp16
__device__ __half g_comb[(size_t)NMAX * KDIM];   // [N, 192] fp16 sum|max|min
__device__ __half g_whi[KDIM * OUTC];            // W hi split [192][64]
__device__ __half g_wlo[KDIM * OUTC];            // W lo split

// ---------------- feature fp32 -> fp16 conversion ----------------

__global__ __launch_bounds__(256) void featcvt_kernel(const float* __restrict__ feat, int total4) {
    int i = blockIdx.x * blockDim.x + threadIdx.x;
    if (i < total4) {
        float4 v = *(const float4*)&feat[(size_t)i * 4];
        __half2 h0 = __floats2half2_rn(v.x, v.y);
        __half2 h1 = __floats2half2_rn(v.z, v.w);
        uint2 u;
        u.x = *(uint32_t*)&h0;
        u.y = *(uint32_t*)&h1;
        g_feat16[i] = u;
    }
}

// ---------------- W hi/lo split ----------------

__global__ __launch_bounds__(256) void wprep_kernel(const float* __restrict__ W) {
    int i = blockIdx.x * blockDim.x + threadIdx.x;
    if (i < KDIM * OUTC) {
        float w = W[i];
        __half hi = __float2half_rn(w);
        __half lo = __float2half_rn(w - __half2float(hi));
        g_whi[i] = hi;
        g_wlo[i] = lo;
    }
}

// ---------------- CSR build ----------------

__global__ void hist_kernel(const int* __restrict__ row, int E) {
    int i = blockIdx.x * blockDim.x + threadIdx.x;
    if (i < E) atomicAdd(&g_cnt[row[i]], 1);
}

#define SCAN_B 512

__global__ __launch_bounds__(SCAN_B) void scan_partial_kernel(int n) {
    __shared__ int ws[16];
    int blk = blockIdx.x, tid = threadIdx.x;
    int i = blk * SCAN_B + tid;
    int v = (i < n) ? g_cnt[i] : 0;
    if (i < n) g_cnt[i] = 0;
    int lane = tid & 31, wid = tid >> 5;
    int x = v;
    #pragma unroll
    for (int o = 1; o < 32; o <<= 1) {
        int y = __shfl_up_sync(0xffffffffu, x, o);
        if (lane >= o) x += y;
    }
    if (lane == 31) ws[wid] = x;
    __syncthreads();
    if (wid == 0 && lane < 16) {
        int w = ws[lane];
        #pragma unroll
        for (int o = 1; o < 16; o <<= 1) {
            int y = __shfl_up_sync(0x0000ffffu, w, o);
            if (lane >= o) w += y;
        }
        ws[lane] = w;
    }
    __syncthreads();
    int incl = x + (wid > 0 ? ws[wid - 1] : 0);
    if (i < n) g_start[i] = incl - v;
    if (tid == SCAN_B - 1) g_bsum[blk] = incl;
}

__global__ __launch_bounds__(SCAN_B) void scan_add_kernel(int n, int nb) {
    __shared__ int ws[16];
    int bid = blockIdx.x, tid = threadIdx.x;
    int lane = tid & 31, wid = tid >> 5;

    int v = (tid < bid) ? g_bsum[tid] : 0;
    #pragma unroll
    for (int o = 16; o > 0; o >>= 1) v += __shfl_down_sync(0xffffffffu, v, o);
    if (lane == 0) ws[wid] = v;
    __syncthreads();
    if (wid == 0) {
        int w = (lane < 16) ? ws[lane] : 0;
        #pragma unroll
        for (int o = 8; o > 0; o >>= 1) w += __shfl_down_sync(0xffffffffu, w, o);
        if (lane == 0) ws[0] = w;
    }
    __syncthreads();
    int off = ws[0];

    int i = bid * SCAN_B + tid;
    if (i < n) {
        int s = g_start[i] + off;
        g_start[i] = s;
        g_cursor[i] = s;
    }
    if (tid == 0 && bid == nb - 1) g_start[n] = off + g_bsum[bid];
}

__global__ void scatter_kernel(const int* __restrict__ row,
                               const int* __restrict__ col, int E) {
    int i = blockIdx.x * blockDim.x + threadIdx.x;
    if (i < E) {
        int p = atomicAdd(&g_cursor[row[i]], 1);
        g_adj[p] = col[i];
    }
}

// ---------------- aggregation: half-warp per node, fp16 in/out ----------------

__device__ __forceinline__ void acc16(float4& sm, __half2& mxa, __half2& mxb,
                                      __half2& mna, __half2& mnb, uint2 u) {
    __half2 h0 = *(__half2*)&u.x;
    __half2 h1 = *(__half2*)&u.y;
    mxa = __hmax2(mxa, h0);  mxb = __hmax2(mxb, h1);
    mna = __hmin2(mna, h0);  mnb = __hmin2(mnb, h1);
    float2 f0 = __half22float2(h0);
    float2 f1 = __half22float2(h1);
    sm.x += f0.x;  sm.y += f0.y;  sm.z += f1.x;  sm.w += f1.y;
}

__global__ __launch_bounds__(256) void aggregate_kernel(int n) {
    int gt   = blockIdx.x * blockDim.x + threadIdx.x;
    int node = gt >> 4;
    int lane = gt & 15;
    if (node >= n) return;

    int s = g_start[node];
    int e = g_start[node + 1];

    float4 sm = make_float4(0.f, 0.f, 0.f, 0.f);
    __half2 ninf2 = __float2half2_rn(-INFINITY);
    __half2 pinf2 = __float2half2_rn( INFINITY);
    __half2 mxa = ninf2, mxb = ninf2;
    __half2 mna = pinf2, mnb = pinf2;

    int j = s;
    for (; j + 4 <= e; j += 4) {
        int c0 = __ldg(&g_adj[j]);
        int c1 = __ldg(&g_adj[j + 1]);
        int c2 = __ldg(&g_adj[j + 2]);
        int c3 = __ldg(&g_adj[j + 3]);
        uint2 u0 = g_feat16[(size_t)c0 * 16 + lane];
        uint2 u1 = g_feat16[(size_t)c1 * 16 + lane];
        uint2 u2 = g_feat16[(size_t)c2 * 16 + lane];
        uint2 u3 = g_feat16[(size_t)c3 * 16 + lane];
        acc16(sm, mxa, mxb, mna, mnb, u0);
        acc16(sm, mxa, mxb, mna, mnb, u1);
        acc16(sm, mxa, mxb, mna, mnb, u2);
        acc16(sm, mxa, mxb, mna, mnb, u3);
    }
    for (; j < e; j++) {
        int c0 = __ldg(&g_adj[j]);
        uint2 u0 = g_feat16[(size_t)c0 * 16 + lane];
        acc16(sm, mxa, mxb, mna, mnb, u0);
    }

    if (e == s) {
        __half2 z = __float2half2_rn(0.f);
        mxa = z; mxb = z; mna = z; mnb = z;
    }

    __half2 s01 = __floats2half2_rn(sm.x, sm.y);
    __half2 s23 = __floats2half2_rn(sm.z, sm.w);
    uint2 sw, xw, nw;
    sw.x = *(uint32_t*)&s01;  sw.y = *(uint32_t*)&s23;
    xw.x = *(uint32_t*)&mxa;  xw.y = *(uint32_t*)&mxb;
    nw.x = *(uint32_t*)&mna;  nw.y = *(uint32_t*)&mnb;
    __half* cb = &g_comb[(size_t)node * KDIM];
    *(uint2*)&cb[        4 * lane] = sw;
    *(uint2*)&cb[ D  +   4 * lane] = xw;
    *(uint2*)&cb[2*D +   4 * lane] = nw;
}

// ---------------- MLP GEMM via mma.sync m16n8k16 (HMMA), fp32 accum ----------------
// BM=128 rows/CTA, 256 threads (8 warps: warp_m=wid>>1 owns 32 rows, warp_n=wid&1
// owns 32 cols). Full K=192 in smem. D = A*Whi + A*Wlo, fp32 accumulators.

__device__ __forceinline__ float tanh_fast(float x) {
    float y; asm("tanh.approx.f32 %0, %1;" : "=f"(y) : "f"(x)); return y;
}
__device__ __forceinline__ uint32_t smem_u32(const void* p) {
    uint32_t a;
    asm("{ .reg .u64 t; cvta.to.shared.u64 t, %1; cvt.u32.u64 %0, t; }" : "=r"(a) : "l"(p));
    return a;
}

#define GBM 128
#define SA_STR 200                   // halfs per A smem row (pad: conflict-free ldmatrix)
#define SW_STR 72                    // halfs per W smem row
#define SM_A 0
#define SM_WHI (GBM * SA_STR)                       // 25600 halfs
#define SM_WLO (SM_WHI + KDIM * SW_STR)             // +13824
#define GEMM_SMEM_HALFS (SM_WLO + KDIM * SW_STR)    // 53248 halfs
#define GEMM_SMEM_BYTES (GEMM_SMEM_HALFS * 2)       // 106496 B

__global__ __launch_bounds__(256) void mlp_gemm_kernel(
    const float* __restrict__ bg, float* __restrict__ out, int n)
{
    extern __shared__ __half smh[];
    int tid = threadIdx.x;
    int block_m = blockIdx.x * GBM;

    // ---- load A tile [128][192] fp16 -> smem (padded stride 200) ----
    #pragma unroll
    for (int i = 0; i < 12; i++) {
        int c = tid + 256 * i;           // 3072 chunks of 8 halfs
        int r = c / 24, c8 = c % 24;
        int gm = block_m + r;
        uint4 v = make_uint4(0u, 0u, 0u, 0u);
        if (gm < n) v = *(const uint4*)&g_comb[(size_t)gm * KDIM + c8 * 8];
        *(uint4*)&smh[SM_A + r * SA_STR + c8 * 8] = v;
    }
    // ---- load Whi/Wlo [192][64] -> smem (padded stride 72) ----
    #pragma unroll
    for (int i = 0; i < 6; i++) {
        int c = tid + 256 * i;           // 1536 chunks
        int r = c / 8, c8 = c % 8;
        *(uint4*)&smh[SM_WHI + r * SW_STR + c8 * 8] = *(const uint4*)&g_whi[r * OUTC + c8 * 8];
        *(uint4*)&smh[SM_WLO + r * SW_STR + c8 * 8] = *(const uint4*)&g_wlo[r * OUTC + c8 * 8];
    }
    __syncthreads();

    int lane = tid & 31;
    int wid = tid >> 5;
    int warp_m = wid >> 1;               // 0..3 -> rows warp_m*32
    int warp_n = wid & 1;                // 0..1 -> cols warp_n*32

    float acc[2][4][4];
    #pragma unroll
    for (int mt = 0; mt < 2; mt++)
        #pragma unroll
        for (int nt = 0; nt < 4; nt++)
            #pragma unroll
            for (int q = 0; q < 4; q++) acc[mt][nt][q] = 0.f;

    // ldmatrix lane addressing
    int a_row = warp_m * 32 + (lane & 15);           // + mt*16
    int a_koff = (lane >> 4) * 8;                    // + k0
    int b_krow = (lane & 7) + ((lane >> 3) & 1) * 8; // + k0
    uint32_t sA = smem_u32(smh);

    #pragma unroll
    for (int ks = 0; ks < 12; ks++) {
        int k0 = ks * 16;
        uint32_t a[2][4];
        #pragma unroll
        for (int mt = 0; mt < 2; mt++) {
            uint32_t addr = sA + 2 * ((a_row + mt * 16) * SA_STR + k0 + a_koff);
            asm volatile("ldmatrix.sync.aligned.m8n8.x4.shared.b16 {%0,%1,%2,%3}, [%4];"
                : "=r"(a[mt][0]), "=r"(a[mt][1]), "=r"(a[mt][2]), "=r"(a[mt][3]) : "r"(addr));
        }
        #pragma unroll
        for (int nt = 0; nt < 4; nt++) {
            int colb = warp_n * 32 + nt * 8;
            uint32_t addr_h = sA + 2 * (SM_WHI + (k0 + b_krow) * SW_STR + colb);
            uint32_t addr_l = sA + 2 * (SM_WLO + (k0 + b_krow) * SW_STR + colb);
            uint32_t bh0, bh1, bl0, bl1;
            asm volatile("ldmatrix.sync.aligned.m8n8.x2.trans.shared.b16 {%0,%1}, [%2];"
                : "=r"(bh0), "=r"(bh1) : "r"(addr_h));
            asm volatile("ldmatrix.sync.aligned.m8n8.x2.trans.shared.b16 {%0,%1}, [%2];"
                : "=r"(bl0), "=r"(bl1) : "r"(addr_l));
            #pragma unroll
            for (int mt = 0; mt < 2; mt++) {
                asm volatile(
                    "mma.sync.aligned.m16n8k16.row.col.f32.f16.f16.f32 "
                    "{%0,%1,%2,%3}, {%4,%5,%6,%7}, {%8,%9}, {%0,%1,%2,%3};"
                    : "+f"(acc[mt][nt][0]), "+f"(acc[mt][nt][1]),
                      "+f"(acc[mt][nt][2]), "+f"(acc[mt][nt][3])
                    : "r"(a[mt][0]), "r"(a[mt][1]), "r"(a[mt][2]), "r"(a[mt][3]),
                      "r"(bh0), "r"(bh1));
                asm volatile(
                    "mma.sync.aligned.m16n8k16.row.col.f32.f16.f16.f32 "
                    "{%0,%1,%2,%3}, {%4,%5,%6,%7}, {%8,%9}, {%0,%1,%2,%3};"
                    : "+f"(acc[mt][nt][0]), "+f"(acc[mt][nt][1]),
                      "+f"(acc[mt][nt][2]), "+f"(acc[mt][nt][3])
                    : "r"(a[mt][0]), "r"(a[mt][1]), "r"(a[mt][2]), "r"(a[mt][3]),
                      "r"(bl0), "r"(bl1));
            }
        }
    }

    // ---- epilogue: bias + tanh -> out ----
    int gid = lane >> 2, tig = lane & 3;
    #pragma unroll
    for (int mt = 0; mt < 2; mt++) {
        #pragma unroll
        for (int nt = 0; nt < 4; nt++) {
            int cbase = warp_n * 32 + nt * 8 + 2 * tig;
            float bx = bg[cbase], by = bg[cbase + 1];
            int r0 = block_m + warp_m * 32 + mt * 16 + gid;
            if (r0 < n) {
                float2 o;
                o.x = tanh_fast(acc[mt][nt][0] + bx);
                o.y = tanh_fast(acc[mt][nt][1] + by);
                *(float2*)&out[(size_t)r0 * OUTC + cbase] = o;
            }
            int r1 = r0 + 8;
            if (r1 < n) {
                float2 o;
                o.x = tanh_fast(acc[mt][nt][2] + bx);
                o.y = tanh_fast(acc[mt][nt][3] + by);
                *(float2*)&out[(size_t)r1 * OUTC + cbase] = o;
            }
        }
    }
}

// ---------------- launch ----------------

extern "C" void kernel_launch(void* const* d_in, const int* in_sizes, int n_in,
                              void* d_out, int out_size) {
    const int*   row  = (const int*)d_in[0];
    const int*   col  = (const int*)d_in[1];
    const float* feat = (const float*)d_in[2];
    const float* W    = (const float*)d_in[3];
    const float* b    = (const float*)d_in[4];
    float* out = (float*)d_out;

    int E = in_sizes[0];
    int N = in_sizes[2] / D;
    int nb = (N + SCAN_B - 1) / SCAN_B;
    int total4 = N * D / 4;

    cudaFuncSetAttribute(mlp_gemm_kernel,
                         cudaFuncAttributeMaxDynamicSharedMemorySize, GEMM_SMEM_BYTES);

    featcvt_kernel<<<(total4 + 255) / 256, 256>>>(feat, total4);
    wprep_kernel<<<(KDIM * OUTC + 255) / 256, 256>>>(W);
    hist_kernel<<<(E + 255) / 256, 256>>>(row, E);
    scan_partial_kernel<<<nb, SCAN_B>>>(N);
    scan_add_kernel<<<nb, SCAN_B>>>(N, nb);
    scatter_kernel<<<(E + 255) / 256, 256>>>(row, col, E);
    aggregate_kernel<<<(N * 16 + 255) / 256, 256>>>(N);
    mlp_gemm_kernel<<<(N + GBM - 1) / GBM, 256, GEMM_SMEM_BYTES>>>(b, out, N);
}

// round 15
// speedup vs baseline: 1.8472x; 1.0447x over previous
#include <cuda_runtime.h>
#include <cuda_fp16.h>
#include <math.h>
#include <cstdint>

#define NMAX 100000
#define EMAX 1600000
#define D 64
#define KDIM 192
#define OUTC 64

typedef unsigned long long u64;

// ---- scratch ----
__device__ int    g_cnt[NMAX];          // zero-init; self-cleaned by scan
__device__ int    g_start[NMAX + 1];
__device__ int    g_cursor[NMAX];
__device__ int    g_adj[EMAX];
__device__ u64    g_desc[256];          // lookback descriptors; reset by scatter
__device__ uint2  g_feat16[(size_t)NMAX * 16];   // [N, 64] fp16
__device__ __half g_comb[(size_t)NMAX * KDIM];   // [N, 192] fp16 sum|max|min
__device__ __half g_whi[KDIM * OUTC];            // W hi split [192][64]
__device__ __half g_wlo[KDIM * OUTC];            // W lo split

// ---------------- prep: feature fp32->fp16 + degree histogram ----------------

__global__ __launch_bounds__(256) void prep_kernel(const float* __restrict__ feat,
                                                   const int* __restrict__ row,
                                                   int total4, int E) {
    int i = blockIdx.x * blockDim.x + threadIdx.x;
    if (i < total4) {
        float4 v = *(const float4*)&feat[(size_t)i * 4];
        __half2 h0 = __floats2half2_rn(v.x, v.y);
        __half2 h1 = __floats2half2_rn(v.z, v.w);
        uint2 u;
        u.x = *(uint32_t*)&h0;
        u.y = *(uint32_t*)&h1;
        g_feat16[i] = u;
    }
    if (i < E) atomicAdd(&g_cnt[row[i]], 1);
}

// ---------------- W hi/lo split ----------------

__global__ __launch_bounds__(256) void wprep_kernel(const float* __restrict__ W) {
    int i = blockIdx.x * blockDim.x + threadIdx.x;
    if (i < KDIM * OUTC) {
        float w = W[i];
        __half hi = __float2half_rn(w);
        __half lo = __float2half_rn(w - __half2float(hi));
        g_whi[i] = hi;
        g_wlo[i] = lo;
    }
}

// ---------------- single-pass decoupled-lookback scan ----------------

#define SCAN_B 512

__global__ __launch_bounds__(SCAN_B) void scan_lookback_kernel(int n, int nb) {
    __shared__ int ws[16];
    __shared__ int s_off;
    int bid = blockIdx.x, tid = threadIdx.x;
    int lane = tid & 31, wid = tid >> 5;
    int i = bid * SCAN_B + tid;

    int v = (i < n) ? g_cnt[i] : 0;
    if (i < n) g_cnt[i] = 0;                    // self-clean for next call

    // block-local scan
    int x = v;
    #pragma unroll
    for (int o = 1; o < 32; o <<= 1) {
        int y = __shfl_up_sync(0xffffffffu, x, o);
        if (lane >= o) x += y;
    }
    if (lane == 31) ws[wid] = x;
    __syncthreads();
    if (wid == 0 && lane < 16) {
        int w = ws[lane];
        #pragma unroll
        for (int o = 1; o < 16; o <<= 1) {
            int y = __shfl_up_sync(0x0000ffffu, w, o);
            if (lane >= o) w += y;
        }
        ws[lane] = w;
    }
    __syncthreads();
    int incl = x + (wid > 0 ? ws[wid - 1] : 0);
    int agg = ws[15];                           // block total

    // publish aggregate (block 0 publishes full prefix immediately)
    if (tid == 0) {
        u64 d = ((u64)(bid == 0 ? 2u : 1u) << 32) | (unsigned)agg;
        *((volatile u64*)&g_desc[bid]) = d;
        __threadfence();
        if (bid == 0) s_off = 0;
    }

    // warp 0: lookback
    if (bid > 0 && wid == 0) {
        int lookbase = bid - 1;
        int run = 0;
        while (true) {
            int idx = lookbase - lane;
            u64 d;
            bool ready;
            do {
                d = (idx >= 0) ? *((volatile u64*)&g_desc[idx]) : (2ull << 32);
                ready = (unsigned)(d >> 32) != 0u;
            } while (!__all_sync(0xffffffffu, ready));
            unsigned pm = __ballot_sync(0xffffffffu, (unsigned)(d >> 32) == 2u);
            int val = (int)(unsigned)(d & 0xffffffffu);
            if (pm) {
                int fp = __ffs(pm) - 1;         // nearest full prefix
                int contrib = (lane <= fp) ? val : 0;
                #pragma unroll
                for (int o = 16; o > 0; o >>= 1)
                    contrib += __shfl_down_sync(0xffffffffu, contrib, o);
                if (lane == 0) {
                    s_off = run + contrib;
                    u64 dn = (2ull << 32) | (unsigned)(run + contrib + agg);
                    *((volatile u64*)&g_desc[bid]) = dn;
                    __threadfence();
                }
                break;
            } else {
                int contrib = val;
                #pragma unroll
                for (int o = 16; o > 0; o >>= 1)
                    contrib += __shfl_down_sync(0xffffffffu, contrib, o);
                contrib = __shfl_sync(0xffffffffu, contrib, 0);
                run += contrib;
                lookbase -= 32;
            }
        }
    }
    __syncthreads();
    int off = s_off;

    if (i < n) {
        int s = incl - v + off;
        g_start[i] = s;
        g_cursor[i] = s;
    }
    if (tid == 0 && bid == nb - 1) g_start[n] = off + agg;
}

// ---------------- scatter (also resets lookback descriptors) ----------------

__global__ void scatter_kernel(const int* __restrict__ row,
                               const int* __restrict__ col, int E) {
    int i = blockIdx.x * blockDim.x + threadIdx.x;
    if (i < 256) g_desc[i] = 0ull;              // reset for next call
    if (i < E) {
        int p = atomicAdd(&g_cursor[row[i]], 1);
        g_adj[p] = col[i];
    }
}

// ---------------- aggregation: half-warp per node, fp16 in/out ----------------

__device__ __forceinline__ void acc16(float4& sm, __half2& mxa, __half2& mxb,
                                      __half2& mna, __half2& mnb, uint2 u) {
    __half2 h0 = *(__half2*)&u.x;
    __half2 h1 = *(__half2*)&u.y;
    mxa = __hmax2(mxa, h0);  mxb = __hmax2(mxb, h1);
    mna = __hmin2(mna, h0);  mnb = __hmin2(mnb, h1);
    float2 f0 = __half22float2(h0);
    float2 f1 = __half22float2(h1);
    sm.x += f0.x;  sm.y += f0.y;  sm.z += f1.x;  sm.w += f1.y;
}

__global__ __launch_bounds__(256) void aggregate_kernel(int n) {
    int gt   = blockIdx.x * blockDim.x + threadIdx.x;
    int node = gt >> 4;
    int lane = gt & 15;
    if (node >= n) return;

    int s = g_start[node];
    int e = g_start[node + 1];

    float4 sm = make_float4(0.f, 0.f, 0.f, 0.f);
    __half2 ninf2 = __float2half2_rn(-INFINITY);
    __half2 pinf2 = __float2half2_rn( INFINITY);
    __half2 mxa = ninf2, mxb = ninf2;
    __half2 mna = pinf2, mnb = pinf2;

    int j = s;
    for (; j + 4 <= e; j += 4) {
        int c0 = __ldg(&g_adj[j]);
        int c1 = __ldg(&g_adj[j + 1]);
        int c2 = __ldg(&g_adj[j + 2]);
        int c3 = __ldg(&g_adj[j + 3]);
        uint2 u0 = g_feat16[(size_t)c0 * 16 + lane];
        uint2 u1 = g_feat16[(size_t)c1 * 16 + lane];
        uint2 u2 = g_feat16[(size_t)c2 * 16 + lane];
        uint2 u3 = g_feat16[(size_t)c3 * 16 + lane];
        acc16(sm, mxa, mxb, mna, mnb, u0);
        acc16(sm, mxa, mxb, mna, mnb, u1);
        acc16(sm, mxa, mxb, mna, mnb, u2);
        acc16(sm, mxa, mxb, mna, mnb, u3);
    }
    for (; j < e; j++) {
        int c0 = __ldg(&g_adj[j]);
        uint2 u0 = g_feat16[(size_t)c0 * 16 + lane];
        acc16(sm, mxa, mxb, mna, mnb, u0);
    }

    if (e == s) {
        __half2 z = __float2half2_rn(0.f);
        mxa = z; mxb = z; mna = z; mnb = z;
    }

    __half2 s01 = __floats2half2_rn(sm.x, sm.y);
    __half2 s23 = __floats2half2_rn(sm.z, sm.w);
    uint2 sw, xw, nw;
    sw.x = *(uint32_t*)&s01;  sw.y = *(uint32_t*)&s23;
    xw.x = *(uint32_t*)&mxa;  xw.y = *(uint32_t*)&mxb;
    nw.x = *(uint32_t*)&mna;  nw.y = *(uint32_t*)&mnb;
    __half* cb = &g_comb[(size_t)node * KDIM];
    *(uint2*)&cb[        4 * lane] = sw;
    *(uint2*)&cb[ D  +   4 * lane] = xw;
    *(uint2*)&cb[2*D +   4 * lane] = nw;
}

// ---------------- MLP GEMM via mma.sync m16n8k16 (HMMA), fp32 accum ----------------

__device__ __forceinline__ float tanh_fast(float x) {
    float y; asm("tanh.approx.f32 %0, %1;" : "=f"(y) : "f"(x)); return y;
}
__device__ __forceinline__ uint32_t smem_u32(const void* p) {
    uint32_t a;
    asm("{ .reg .u64 t; cvta.to.shared.u64 t, %1; cvt.u32.u64 %0, t; }" : "=r"(a) : "l"(p));
    return a;
}

#define GBM 128
#define SA_STR 200
#define SW_STR 72
#define SM_A 0
#define SM_WHI (GBM * SA_STR)
#define SM_WLO (SM_WHI + KDIM * SW_STR)
#define GEMM_SMEM_HALFS (SM_WLO + KDIM * SW_STR)
#define GEMM_SMEM_BYTES (GEMM_SMEM_HALFS * 2)

__global__ __launch_bounds__(256) void mlp_gemm_kernel(
    const float* __restrict__ bg, float* __restrict__ out, int n)
{
    extern __shared__ __half smh[];
    int tid = threadIdx.x;
    int block_m = blockIdx.x * GBM;

    #pragma unroll
    for (int i = 0; i < 12; i++) {
        int c = tid + 256 * i;
        int r = c / 24, c8 = c % 24;
        int gm = block_m + r;
        uint4 v = make_uint4(0u, 0u, 0u, 0u);
        if (gm < n) v = *(const uint4*)&g_comb[(size_t)gm * KDIM + c8 * 8];
        *(uint4*)&smh[SM_A + r * SA_STR + c8 * 8] = v;
    }
    #pragma unroll
    for (int i = 0; i < 6; i++) {
        int c = tid + 256 * i;
        int r = c / 8, c8 = c % 8;
        *(uint4*)&smh[SM_WHI + r * SW_STR + c8 * 8] = *(const uint4*)&g_whi[r * OUTC + c8 * 8];
        *(uint4*)&smh[SM_WLO + r * SW_STR + c8 * 8] = *(const uint4*)&g_wlo[r * OUTC + c8 * 8];
    }
    __syncthreads();

    int lane = tid & 31;
    int wid = tid >> 5;
    int warp_m = wid >> 1;
    int warp_n = wid & 1;

    float acc[2][4][4];
    #pragma unroll
    for (int mt = 0; mt < 2; mt++)
        #pragma unroll
        for (int nt = 0; nt < 4; nt++)
            #pragma unroll
            for (int q = 0; q < 4; q++) acc[mt][nt][q] = 0.f;

    int a_row = warp_m * 32 + (lane & 15);
    int a_koff = (lane >> 4) * 8;
    int b_krow = (lane & 7) + ((lane >> 3) & 1) * 8;
    uint32_t sA = smem_u32(smh);

    #pragma unroll
    for (int ks = 0; ks < 12; ks++) {
        int k0 = ks * 16;
        uint32_t a[2][4];
        #pragma unroll
        for (int mt = 0; mt < 2; mt++) {
            uint32_t addr = sA + 2 * ((a_row + mt * 16) * SA_STR + k0 + a_koff);
            asm volatile("ldmatrix.sync.aligned.m8n8.x4.shared.b16 {%0,%1,%2,%3}, [%4];"
                : "=r"(a[mt][0]), "=r"(a[mt][1]), "=r"(a[mt][2]), "=r"(a[mt][3]) : "r"(addr));
        }
        #pragma unroll
        for (int nt = 0; nt < 4; nt++) {
            int colb = warp_n * 32 + nt * 8;
            uint32_t addr_h = sA + 2 * (SM_WHI + (k0 + b_krow) * SW_STR + colb);
            uint32_t addr_l = sA + 2 * (SM_WLO + (k0 + b_krow) * SW_STR + colb);
            uint32_t bh0, bh1, bl0, bl1;
            asm volatile("ldmatrix.sync.aligned.m8n8.x2.trans.shared.b16 {%0,%1}, [%2];"
                : "=r"(bh0), "=r"(bh1) : "r"(addr_h));
            asm volatile("ldmatrix.sync.aligned.m8n8.x2.trans.shared.b16 {%0,%1}, [%2];"
                : "=r"(bl0), "=r"(bl1) : "r"(addr_l));
            #pragma unroll
            for (int mt = 0; mt < 2; mt++) {
                asm volatile(
                    "mma.sync.aligned.m16n8k16.row.col.f32.f16.f16.f32 "
                    "{%0,%1,%2,%3}, {%4,%5,%6,%7}, {%8,%9}, {%0,%1,%2,%3};"
                    : "+f"(acc[mt][nt][0]), "+f"(acc[mt][nt][1]),
                      "+f"(acc[mt][nt][2]), "+f"(acc[mt][nt][3])
                    : "r"(a[mt][0]), "r"(a[mt][1]), "r"(a[mt][2]), "r"(a[mt][3]),
                      "r"(bh0), "r"(bh1));
                asm volatile(
                    "mma.sync.aligned.m16n8k16.row.col.f32.f16.f16.f32 "
                    "{%0,%1,%2,%3}, {%4,%5,%6,%7}, {%8,%9}, {%0,%1,%2,%3};"
                    : "+f"(acc[mt][nt][0]), "+f"(acc[mt][nt][1]),
                      "+f"(acc[mt][nt][2]), "+f"(acc[mt][nt][3])
                    : "r"(a[mt][0]), "r"(a[mt][1]), "r"(a[mt][2]), "r"(a[mt][3]),
                      "r"(bl0), "r"(bl1));
            }
        }
    }

    int gid = lane >> 2, tig = lane & 3;
    #pragma unroll
    for (int mt = 0; mt < 2; mt++) {
        #pragma unroll
        for (int nt = 0; nt < 4; nt++) {
            int cbase = warp_n * 32 + nt * 8 + 2 * tig;
            float bx = bg[cbase], by = bg[cbase + 1];
            int r0 = block_m + warp_m * 32 + mt * 16 + gid;
            if (r0 < n) {
                float2 o;
                o.x = tanh_fast(acc[mt][nt][0] + bx);
                o.y = tanh_fast(acc[mt][nt][1] + by);
                *(float2*)&out[(size_t)r0 * OUTC + cbase] = o;
            }
            int r1 = r0 + 8;
            if (r1 < n) {
                float2 o;
                o.x = tanh_fast(acc[mt][nt][2] + bx);
                o.y = tanh_fast(acc[mt][nt][3] + by);
                *(float2*)&out[(size_t)r1 * OUTC + cbase] = o;
            }
        }
    }
}

// ---------------- launch ----------------

extern "C" void kernel_launch(void* const* d_in, const int* in_sizes, int n_in,
                              void* d_out, int out_size) {
    const int*   row  = (const int*)d_in[0];
    const int*   col  = (const int*)d_in[1];
    const float* feat = (const float*)d_in[2];
    const float* W    = (const float*)d_in[3];
    const float* b    = (const float*)d_in[4];
    float* out = (float*)d_out;

    int E = in_sizes[0];
    int N = in_sizes[2] / D;
    int nb = (N + SCAN_B - 1) / SCAN_B;
    int total4 = N * D / 4;
    int prep_n = (total4 > E) ? total4 : E;

    cudaFuncSetAttribute(mlp_gemm_kernel,
                         cudaFuncAttributeMaxDynamicSharedMemorySize, GEMM_SMEM_BYTES);

    prep_kernel<<<(prep_n + 255) / 256, 256>>>(feat, row, total4, E);
    wprep_kernel<<<(KDIM * OUTC + 255) / 256, 256>>>(W);
    scan_lookback_kernel<<<nb, SCAN_B>>>(N, nb);
    scatter_kernel<<<(E + 255) / 256, 256>>>(row, col, E);
    aggregate_kernel<<<(N * 16 + 255) / 256, 256>>>(N);
    mlp_gemm_kernel<<<(N + GBM - 1) / GBM, 256, GEMM_SMEM_BYTES>>>(b, out, N);
}